// round 1
// baseline (speedup 1.0000x reference)
#include <cuda_runtime.h>

#define MAXN 50000
#define MAXE 800000
#define SBS  512
#define XP   65
#define G1_BM 64
#define HP   132

// ---------------- scratch (device globals; no allocation allowed) ----------
__device__ __align__(16) float g_h1[MAXN * 128];   // (x@W1) * norm_src
__device__ __align__(16) float g_h2[MAXN * 128];   // relu(agg1*norm_dst + b1)
__device__ __align__(16) float g_h3[MAXN * 8];     // (h2@W2) * norm_src
__device__ __align__(16) float g_nodeout[MAXN * 8];
__device__ int   g_deg_out[MAXN];
__device__ int   g_deg_in[MAXN];
__device__ float g_norm_src[MAXN];
__device__ float g_norm_dst[MAXN];
__device__ int   g_off[MAXN];
__device__ int   g_cursor[MAXN];
__device__ int   g_csr_src[MAXE];
__device__ int   g_partial[256];

// ---------------- degree / norm ----------------
__global__ void k_zero_deg(int n) {
    int i = blockIdx.x * blockDim.x + threadIdx.x;
    if (i < n) { g_deg_out[i] = 0; g_deg_in[i] = 0; }
}

__global__ void k_deg(const int* __restrict__ src, const int* __restrict__ dst, int e) {
    int i = blockIdx.x * blockDim.x + threadIdx.x;
    if (i < e) {
        atomicAdd(&g_deg_out[src[i]], 1);
        atomicAdd(&g_deg_in[dst[i]], 1);
    }
}

__global__ void k_norm(int n) {
    int i = blockIdx.x * blockDim.x + threadIdx.x;
    if (i < n) {
        int a = g_deg_out[i];
        int b = g_deg_in[i];
        g_norm_src[i] = (a > 0) ? rsqrtf((float)a) : 0.f;
        g_norm_dst[i] = (b > 0) ? rsqrtf((float)b) : 0.f;
    }
}

// ---------------- exclusive scan of deg_in -> CSR offsets ----------------
__global__ void k_scan_partial(int n) {
    __shared__ int s[SBS];
    int i = blockIdx.x * SBS + threadIdx.x;
    s[threadIdx.x] = (i < n) ? g_deg_in[i] : 0;
    __syncthreads();
    for (int d = SBS / 2; d > 0; d >>= 1) {
        if (threadIdx.x < d) s[threadIdx.x] += s[threadIdx.x + d];
        __syncthreads();
    }
    if (threadIdx.x == 0) g_partial[blockIdx.x] = s[0];
}

__global__ void k_scan_top(int nb) {
    if (threadIdx.x == 0) {
        int run = 0;
        for (int i = 0; i < nb; ++i) { int v = g_partial[i]; g_partial[i] = run; run += v; }
    }
}

__global__ void k_scan_final(int n) {
    __shared__ int s[SBS];
    int i = blockIdx.x * SBS + threadIdx.x;
    int v = (i < n) ? g_deg_in[i] : 0;
    s[threadIdx.x] = v;
    __syncthreads();
    for (int d = 1; d < SBS; d <<= 1) {
        int tmp = (threadIdx.x >= d) ? s[threadIdx.x - d] : 0;
        __syncthreads();
        s[threadIdx.x] += tmp;
        __syncthreads();
    }
    if (i < n) {
        int ex = g_partial[blockIdx.x] + s[threadIdx.x] - v;
        g_off[i] = ex;
        g_cursor[i] = ex;
    }
}

__global__ void k_fill(const int* __restrict__ src, const int* __restrict__ dst, int e) {
    int i = blockIdx.x * blockDim.x + threadIdx.x;
    if (i < e) {
        int p = atomicAdd(&g_cursor[dst[i]], 1);
        g_csr_src[p] = src[i];
    }
}

// ---------------- GEMM1: g_h1 = (X @ W1) * norm_src[row] ----------------
// block: 256 threads, 64 rows x 128 cols; thread micro-tile 8x4.
__global__ void k_gemm1(const float* __restrict__ X, const float* __restrict__ W, int n) {
    extern __shared__ float sm[];
    float* Ws = sm;               // 128*128
    float* Xs = sm + 128 * 128;   // 128 * XP (k-major, transposed, padded)
    int t = threadIdx.x;
    int row0 = blockIdx.x * G1_BM;

    const float4* W4 = (const float4*)W;
#pragma unroll
    for (int i = 0; i < 16; ++i)
        ((float4*)Ws)[t + 256 * i] = W4[t + 256 * i];

#pragma unroll
    for (int i = 0; i < 8; ++i) {
        int idx = t + 256 * i;        // float4 index: 64 rows x 32 float4
        int r  = idx >> 5;
        int c4 = idx & 31;
        float4 v = make_float4(0.f, 0.f, 0.f, 0.f);
        int grow = row0 + r;
        if (grow < n) v = ((const float4*)X)[grow * 32 + c4];
        int k0 = c4 * 4;
        Xs[(k0 + 0) * XP + r] = v.x;
        Xs[(k0 + 1) * XP + r] = v.y;
        Xs[(k0 + 2) * XP + r] = v.z;
        Xs[(k0 + 3) * XP + r] = v.w;
    }
    __syncthreads();

    int cg = (t & 31) * 4;   // col base
    int rg = (t >> 5) * 8;   // row base
    float acc[8][4] = {};

#pragma unroll 8
    for (int k = 0; k < 128; ++k) {
        float4 b = *(const float4*)(Ws + k * 128 + cg);
#pragma unroll
        for (int r = 0; r < 8; ++r) {
            float a = Xs[k * XP + rg + r];
            acc[r][0] = fmaf(a, b.x, acc[r][0]);
            acc[r][1] = fmaf(a, b.y, acc[r][1]);
            acc[r][2] = fmaf(a, b.z, acc[r][2]);
            acc[r][3] = fmaf(a, b.w, acc[r][3]);
        }
    }

#pragma unroll
    for (int r = 0; r < 8; ++r) {
        int grow = row0 + rg + r;
        if (grow < n) {
            float s = g_norm_src[grow];
            float4 o = make_float4(acc[r][0] * s, acc[r][1] * s, acc[r][2] * s, acc[r][3] * s);
            ((float4*)g_h1)[grow * 32 + (t & 31)] = o;
        }
    }
}

// ---------------- agg1: warp per dst node, 128-dim gather-sum ----------------
__global__ void k_agg1(const float* __restrict__ b1, int n) {
    int w = (blockIdx.x * blockDim.x + threadIdx.x) >> 5;
    int lane = threadIdx.x & 31;
    if (w >= n) return;
    int s = g_off[w];
    int e = s + g_deg_in[w];
    const float4* h14 = (const float4*)g_h1;
    float4 acc = make_float4(0.f, 0.f, 0.f, 0.f);
    int i = s;
    for (; i + 2 <= e; i += 2) {
        int s0 = g_csr_src[i];
        int s1 = g_csr_src[i + 1];
        float4 v0 = h14[s0 * 32 + lane];
        float4 v1 = h14[s1 * 32 + lane];
        acc.x += v0.x + v1.x;
        acc.y += v0.y + v1.y;
        acc.z += v0.z + v1.z;
        acc.w += v0.w + v1.w;
    }
    if (i < e) {
        int s0 = g_csr_src[i];
        float4 v0 = h14[s0 * 32 + lane];
        acc.x += v0.x; acc.y += v0.y; acc.z += v0.z; acc.w += v0.w;
    }
    float nd = g_norm_dst[w];
    float4 bb = ((const float4*)b1)[lane];
    float4 o;
    o.x = fmaxf(fmaf(acc.x, nd, bb.x), 0.f);
    o.y = fmaxf(fmaf(acc.y, nd, bb.y), 0.f);
    o.z = fmaxf(fmaf(acc.z, nd, bb.z), 0.f);
    o.w = fmaxf(fmaf(acc.w, nd, bb.w), 0.f);
    ((float4*)g_h2)[w * 32 + lane] = o;
}

// ---------------- GEMM2: g_h3 = (g_h2 @ W2) * norm_src ----------------
__global__ void k_gemm2(const float* __restrict__ W2, int n) {
    __shared__ float hs[32 * HP];
    __shared__ float ws[128 * 8];
    int t = threadIdx.x;
    int n0 = blockIdx.x * 32;
#pragma unroll
    for (int i = 0; i < 4; ++i) {
        int idx = t + 256 * i;        // 1024 float4 = 32 rows x 32
        int r = idx >> 5, c4 = idx & 31;
        float4 v = make_float4(0.f, 0.f, 0.f, 0.f);
        if (n0 + r < n) v = ((const float4*)g_h2)[(n0 + r) * 32 + c4];
        *(float4*)(hs + r * HP + c4 * 4) = v;
    }
    ((float4*)ws)[t] = ((const float4*)W2)[t];
    __syncthreads();
    int node = t >> 3, j = t & 7;
    int gn = n0 + node;
    float acc = 0.f;
#pragma unroll 8
    for (int k = 0; k < 128; ++k)
        acc = fmaf(hs[node * HP + k], ws[k * 8 + j], acc);
    if (gn < n) g_h3[gn * 8 + j] = acc * g_norm_src[gn];
}

// ---------------- agg2: thread per (node, feature), 8-dim ----------------
__global__ void k_agg2(const float* __restrict__ b2, int n) {
    int idx = blockIdx.x * blockDim.x + threadIdx.x;
    int node = idx >> 3, f = idx & 7;
    if (node >= n) return;
    int s = g_off[node];
    int e = s + g_deg_in[node];
    float acc = 0.f;
    for (int i = s; i < e; ++i)
        acc += g_h3[g_csr_src[i] * 8 + f];
    g_nodeout[node * 8 + f] = fmaf(acc, g_norm_dst[node], b2[f]);
}

// ---------------- per-graph mean pooling (graph_ids sorted) ----------------
__global__ void k_pool(const int* __restrict__ gids, float* __restrict__ out, int n) {
    __shared__ int sse[2];
    int g = blockIdx.x;
    if (threadIdx.x == 0) {
        int lo = 0, hi = n;
        while (lo < hi) { int m = (lo + hi) >> 1; if (gids[m] < g) lo = m + 1; else hi = m; }
        sse[0] = lo;
        lo = 0; hi = n;
        while (lo < hi) { int m = (lo + hi) >> 1; if (gids[m] <= g) lo = m + 1; else hi = m; }
        sse[1] = lo;
    }
    __syncthreads();
    int s = sse[0], e = sse[1];
    float acc[8] = {};
    for (int i = s + threadIdx.x; i < e; i += blockDim.x) {
#pragma unroll
        for (int f = 0; f < 8; ++f) acc[f] += g_nodeout[i * 8 + f];
    }
    __shared__ float red[256 * 8];
#pragma unroll
    for (int f = 0; f < 8; ++f) red[threadIdx.x * 8 + f] = acc[f];
    __syncthreads();
    for (int d = 128; d > 0; d >>= 1) {
        if (threadIdx.x < d) {
#pragma unroll
            for (int f = 0; f < 8; ++f)
                red[threadIdx.x * 8 + f] += red[(threadIdx.x + d) * 8 + f];
        }
        __syncthreads();
    }
    if (threadIdx.x < 8) {
        float cnt = (float)(e - s);
        out[g * 8 + threadIdx.x] = red[threadIdx.x] / fmaxf(cnt, 1.f);
    }
}

// ---------------- launch ----------------
extern "C" void kernel_launch(void* const* d_in, const int* in_sizes, int n_in,
                              void* d_out, int out_size) {
    const float* x   = (const float*)d_in[0];
    const float* W1  = (const float*)d_in[1];
    const float* b1  = (const float*)d_in[2];
    const float* W2  = (const float*)d_in[3];
    const float* b2  = (const float*)d_in[4];
    const int*   src = (const int*)d_in[5];
    const int*   dst = (const int*)d_in[6];
    const int*   gid = (const int*)d_in[7];
    int n  = in_sizes[7];          // graph_ids has one entry per node
    int e  = in_sizes[5];
    int ng = out_size / 8;
    float* out = (float*)d_out;

    k_zero_deg<<<(n + 255) / 256, 256>>>(n);
    k_deg<<<(e + 255) / 256, 256>>>(src, dst, e);
    k_norm<<<(n + 255) / 256, 256>>>(n);

    int nb = (n + SBS - 1) / SBS;
    k_scan_partial<<<nb, SBS>>>(n);
    k_scan_top<<<1, 32>>>(nb);
    k_scan_final<<<nb, SBS>>>(n);
    k_fill<<<(e + 255) / 256, 256>>>(src, dst, e);

    size_t smem = (128 * 128 + 128 * XP) * sizeof(float);
    cudaFuncSetAttribute(k_gemm1, cudaFuncAttributeMaxDynamicSharedMemorySize, (int)smem);
    k_gemm1<<<(n + G1_BM - 1) / G1_BM, 256, smem>>>(x, W1, n);

    k_agg1<<<(n * 32 + 255) / 256, 256>>>(b1, n);
    k_gemm2<<<(n + 31) / 32, 256>>>(W2, n);
    k_agg2<<<(n * 8 + 255) / 256, 256>>>(b2, n);
    k_pool<<<ng, 256>>>(gid, out, n);
}